// round 2
// baseline (speedup 1.0000x reference)
#include <cuda_runtime.h>
#include <math.h>

#define BATCH 32
#define TLEN  1024
#define IDIM  512
#define HDIM  1024
#define G4    4096
#define KTOT  1536            // 512 (x) + 1024 (h)
#define KP_TOT 768            // k-pairs
#define KP_X  256             // k-pairs belonging to x
#define GRID  128
#define NTH   256
#define KPCH  48              // k-pairs per staged chunk (96 k)
#define NCH   16              // 768 / 48
#define WSTR  1540            // padded row stride (floats) for sW (bank spread)

// ---------------- static device scratch (allocation-free) ------------------
__device__ float g_xT[(size_t)TLEN * (IDIM / 2) * BATCH * 2]; // 64MB: [t][i2][b] float2
__device__ float g_h[2][(HDIM / 2) * BATCH * 2];              // [kp][b] float2, double buffered
__device__ volatile unsigned g_bar;                            // monotonic grid barrier
__device__ unsigned g_done;                                    // replay reset counter

// ---------------- helpers ---------------------------------------------------
__device__ __forceinline__ void ffma2(unsigned long long& d,
                                      unsigned long long a,
                                      unsigned long long b) {
    asm("fma.rn.f32x2 %0, %1, %2, %0;" : "+l"(d) : "l"(a), "l"(b));
}
__device__ __forceinline__ float acc_sum(unsigned long long v) {
    return __uint_as_float((unsigned)v) + __uint_as_float((unsigned)(v >> 32));
}
__device__ __forceinline__ float sigm(float x) {
    return 1.f / (1.f + __expf(-x));
}
__device__ __forceinline__ float tanh_f(float x) {
    // tanh(x) = 1 - 2/(exp(2x)+1)
    return 1.f - 2.f / (__expf(2.f * x) + 1.f);
}

// ============ Kernel 0: transpose x[b][t][i] -> g_xT[t][i2][b] float2 ======
__global__ __launch_bounds__(256) void xpose(const float* __restrict__ X) {
    size_t n = (size_t)blockIdx.x * 256 + threadIdx.x;  // over 8,388,608 float2
    int b  = (int)(n & 31);
    size_t r = n >> 5;
    int i2 = (int)(r & 255);
    int t  = (int)(r >> 8);
    float2 v = *(const float2*)(X + ((size_t)b * TLEN + t) * IDIM + 2 * i2);
    ((float2*)g_xT)[n] = v;
}

// ============ Kernel 1: fused persistent LSTM ==============================
// 128 blocks x 256 threads. Block owns 8 hidden units -> 32 gate rows
// (lr = gate*8 + u <-> global row gate*H + blk*8 + u).
// sW row lr = concat(W_ih[grow][0:512], W_hh[grow][0:1024]) (fp32, WSTR stride).
// Warp w: rows 4w..4w+3. Thread: rg=lane>>4 -> rows 4w+2rg, 4w+2rg+1;
// bp=lane&15 -> batches 2bp, 2bp+1. Acc = f32x2 with even/odd-k partials.
__global__ __launch_bounds__(NTH, 1) void lstm_fused(const float* __restrict__ Wih,
                                                     const float* __restrict__ Whh,
                                                     const float* __restrict__ bih,
                                                     const float* __restrict__ bhh,
                                                     float* __restrict__ out) {
    extern __shared__ float smem[];
    float* sW   = smem;                        // 32 * WSTR floats
    float* sBuf = smem + 32 * WSTR;            // 2 * KPCH*64 floats
    __shared__ float sG[32 * 32];
    __shared__ float sBias[32];

    const int tid  = threadIdx.x;
    const int blk  = blockIdx.x;
    const int w    = tid >> 5;
    const int lane = tid & 31;
    const int rg   = lane >> 4;
    const int bp   = lane & 15;
    const int r0   = 4 * w + 2 * rg;           // rows r0, r0+1
    const int uu   = w;                        // epilogue unit-local (8 units)
    const int bb   = lane;                     // epilogue batch
    const int gu   = blk * 8 + uu;

    // ---- init: load W slice, bias, zero h buffer 0 ----
    for (int i = tid; i < 32 * (KTOT / 4); i += NTH) {
        const int lr = i / (KTOT / 4);
        const int kq = i % (KTOT / 4);
        const int g = lr >> 3, u = lr & 7;
        const int grow = g * HDIM + blk * 8 + u;
        float4 v;
        if (kq < IDIM / 4) v = *(const float4*)(Wih + (size_t)grow * IDIM + kq * 4);
        else               v = *(const float4*)(Whh + (size_t)grow * HDIM + (kq - IDIM / 4) * 4);
        *(float4*)(sW + (size_t)lr * WSTR + kq * 4) = v;
    }
    if (tid < 32) {
        const int g = tid >> 3, u = tid & 7;
        const int grow = g * HDIM + blk * 8 + u;
        sBias[tid] = bih[grow] + bhh[grow];
    }
    g_h[0][(gu >> 1) * 64 + bb * 2 + (gu & 1)] = 0.f;
    __threadfence();
    float cstate = 0.f;
    __syncthreads();

    const float* wp0base = sW + (size_t)r0 * WSTR;
    const float* wp1base = wp0base + WSTR;

    for (int t = 0; t < TLEN; ++t) {
        const float4* xs = (const float4*)g_xT + (size_t)t * 4096;
        const float4* hs = (const float4*)(g_h[t & 1]);

        unsigned long long a00 = 0, a01 = 0, a10 = 0, a11 = 0;

        // chunk loader: 3 float4 per thread per chunk (KPCH*32 float2 = 768 float4)
        auto ldchunk = [&](int c, float4& p0, float4& p1, float4& p2) {
            int e = tid;
#pragma unroll
            for (int j = 0; j < 3; ++j) {
                const int kp = c * KPCH + (e >> 4);
                const int q  = e & 15;
                float4 v;
                if (kp < KP_X) v = __ldcg(xs + (size_t)kp * 16 + q);
                else           v = __ldcg(hs + (size_t)(kp - KP_X) * 16 + q);
                if (j == 0) p0 = v; else if (j == 1) p1 = v; else p2 = v;
                e += 256;
            }
        };

        float4 pf0, pf1, pf2;
        ldchunk(0, pf0, pf1, pf2);

        for (int c = 0; c < NCH; ++c) {
            float* buf = sBuf + (c & 1) * (KPCH * 64);
            __syncthreads();                       // buf consumers (chunk c-2) done
            {
                float4* b4 = (float4*)buf;
                b4[tid] = pf0; b4[tid + 256] = pf1; b4[tid + 512] = pf2;
            }
            __syncthreads();                       // staged data visible

            if (c == 4) {
                // grid barrier before first h-dependent prefetch (chunk 5).
                // x-chunks 0..4 already computed -> barrier wait overlaps work.
                if (tid == 0) {
                    __threadfence();
                    atomicAdd((unsigned*)&g_bar, 1u);
                    const unsigned target = (unsigned)(t + 1) * GRID;
                    while (*(volatile unsigned*)&g_bar < target) { }
                    __threadfence();
                }
                __syncthreads();
            }
            if (c + 1 < NCH) ldchunk(c + 1, pf0, pf1, pf2);  // overlaps compute

            const float* wp0 = wp0base + 2 * (c * KPCH);
            const float* wp1 = wp1base + 2 * (c * KPCH);
#pragma unroll 4
            for (int jj = 0; jj < KPCH; jj += 2) {
                ulonglong2 wv0 = *(const ulonglong2*)(wp0 + 2 * jj);   // rows r0:   k..k+3
                ulonglong2 wv1 = *(const ulonglong2*)(wp1 + 2 * jj);   // rows r0+1: k..k+3
                ulonglong2 h0  = *(const ulonglong2*)(buf + jj * 64 + 4 * bp);       // kp jj,  b0|b1
                ulonglong2 h1  = *(const ulonglong2*)(buf + (jj + 1) * 64 + 4 * bp); // kp jj+1
                ffma2(a00, wv0.x, h0.x); ffma2(a01, wv0.x, h0.y);
                ffma2(a10, wv1.x, h0.x); ffma2(a11, wv1.x, h0.y);
                ffma2(a00, wv0.y, h1.x); ffma2(a01, wv0.y, h1.y);
                ffma2(a10, wv1.y, h1.x); ffma2(a11, wv1.y, h1.y);
            }
        }

        // ---- publish gate pre-activations ----
        sG[r0 * 32 + 2 * bp]           = acc_sum(a00);
        sG[r0 * 32 + 2 * bp + 1]       = acc_sum(a01);
        sG[(r0 + 1) * 32 + 2 * bp]     = acc_sum(a10);
        sG[(r0 + 1) * 32 + 2 * bp + 1] = acc_sum(a11);
        __syncthreads();

        // ---- cell update: thread (uu, bb) ----
        const float pi = sG[(0 * 8 + uu) * 32 + bb] + sBias[0 * 8 + uu];
        const float pf = sG[(1 * 8 + uu) * 32 + bb] + sBias[1 * 8 + uu];
        const float pg = sG[(2 * 8 + uu) * 32 + bb] + sBias[2 * 8 + uu];
        const float po = sG[(3 * 8 + uu) * 32 + bb] + sBias[3 * 8 + uu];

        const float ig = sigm(pi);
        const float fg = sigm(pf);
        const float gg = tanh_f(pg);
        const float og = sigm(po);

        const float cnew = fmaf(fg, cstate, ig * gg);
        cstate = cnew;
        const float hnew = og * tanh_f(cnew);

        g_h[(t + 1) & 1][(gu >> 1) * 64 + bb * 2 + (gu & 1)] = hnew;
        out[(size_t)bb * TLEN * HDIM + (size_t)t * HDIM + gu] = hnew;
        if (t == TLEN - 1) {
            const size_t OFF = (size_t)BATCH * TLEN * HDIM;
            out[OFF + (size_t)bb * HDIM + gu] = hnew;                  // h_T
            out[OFF + BATCH * HDIM + (size_t)bb * HDIM + gu] = cnew;   // c_T
        }
        __threadfence();   // h visible before this block's next-step arrive
    }

    // ---- reset barrier state for graph replays ----
    __syncthreads();
    if (tid == 0) {
        const unsigned d = atomicAdd(&g_done, 1u);
        if (d == GRID - 1) {
            g_bar = 0;
            g_done = 0;
            __threadfence();
        }
    }
}

// =========================== launch ========================================
extern "C" void kernel_launch(void* const* d_in, const int* in_sizes, int n_in,
                              void* d_out, int out_size) {
    const float* X   = (const float*)d_in[0];   // [32,1024,512]
    const float* Wih = (const float*)d_in[1];   // [4096,512]
    const float* Whh = (const float*)d_in[2];   // [4096,1024]
    const float* bih = (const float*)d_in[3];   // [4096]
    const float* bhh = (const float*)d_in[4];   // [4096]
    float* out = (float*)d_out;

    const int dyn_smem = (32 * WSTR + 2 * KPCH * 64) * (int)sizeof(float); // 221,696 B
    cudaFuncSetAttribute(lstm_fused, cudaFuncAttributeMaxDynamicSharedMemorySize, dyn_smem);

    xpose<<<(TLEN * (IDIM / 2) * BATCH) / 256, 256>>>(X);
    lstm_fused<<<GRID, NTH, dyn_smem>>>(Wih, Whh, bih, bhh, out);
}

// round 7
// speedup vs baseline: 1.4690x; 1.4690x over previous
#include <cuda_runtime.h>
#include <cstdint>
#include <math.h>

#define BATCH 32
#define TLEN  1024
#define IDIM  512
#define HDIM  1024
#define G4    4096
#define KP    512          // k-pairs in recurrence (HDIM/2)
#define KPCH  128          // k-pairs per staged chunk
#define NCH   4
#define GRID  128
#define NTH   128

// ---------------- static device scratch (allocation-free) ------------------
__device__ float g_Xg[(size_t)BATCH * TLEN * G4];   // [t*32+b][4096], includes biases
__device__ float g_h[2][HDIM * BATCH];              // [kp][b] float2: idx kp*64 + b*2 + par
__device__ volatile unsigned g_bar;
__device__ unsigned g_done;

// ---------------- helpers ---------------------------------------------------
__device__ __forceinline__ void ffma2(unsigned long long& d,
                                      unsigned long long a,
                                      unsigned long long b) {
    asm("fma.rn.f32x2 %0, %1, %2, %0;" : "+l"(d) : "l"(a), "l"(b));
}
__device__ __forceinline__ float acc_sum(unsigned long long v) {
    return __uint_as_float((unsigned)v) + __uint_as_float((unsigned)(v >> 32));
}
__device__ __forceinline__ float sigm(float x) { return 1.f / (1.f + __expf(-x)); }
__device__ __forceinline__ float tanh_f(float x) { return 1.f - 2.f / (__expf(2.f * x) + 1.f); }

__device__ __forceinline__ void cp16(unsigned int saddr, const void* g) {
    asm volatile("cp.async.cg.shared.global [%0], [%1], 16;" :: "r"(saddr), "l"(g));
}
#define CP_COMMIT() asm volatile("cp.async.commit_group;" ::: "memory")
#define CP_WAIT(n)  asm volatile("cp.async.wait_group %0;" :: "n"(n) : "memory")

// ======================= Kernel 1: Xg = X @ W_ih^T + (b_ih + b_hh) =========
#define BM 128
#define BN 64
#define BK 16
#define SAS 18
#define SBS 18

__global__ __launch_bounds__(256) void xg_gemm(const float* __restrict__ X,
                                               const float* __restrict__ Wih,
                                               const float* __restrict__ bih,
                                               const float* __restrict__ bhh) {
    __shared__ float sA[BM * SAS];
    __shared__ float sB[BN * SBS];

    const int tid = threadIdx.x;
    const int tx = tid & 15;
    const int ty = tid >> 4;
    const int n0 = blockIdx.y * BM;
    const int c0 = blockIdx.x * BN;

    unsigned long long acc2[8][4];
#pragma unroll
    for (int i = 0; i < 8; ++i)
#pragma unroll
        for (int j = 0; j < 4; ++j) acc2[i][j] = 0ull;

    for (int k0 = 0; k0 < IDIM; k0 += BK) {
        {   // A tile: 128x16, 8 floats/thread
            const int m = tid >> 1;
            const int kk = (tid & 1) * 8;
            const float* src = X + (size_t)(n0 + m) * IDIM + k0 + kk;
            float4 v0 = *(const float4*)(src);
            float4 v1 = *(const float4*)(src + 4);
            float* d = sA + m * SAS + kk;
            d[0] = v0.x; d[1] = v0.y; d[2] = v0.z; d[3] = v0.w;
            d[4] = v1.x; d[5] = v1.y; d[6] = v1.z; d[7] = v1.w;
        }
        {   // B tile: 64x16, 4 floats/thread
            const int m = tid >> 2;
            const int kk = (tid & 3) * 4;
            float4 v = *(const float4*)(Wih + (size_t)(c0 + m) * IDIM + k0 + kk);
            float* d = sB + m * SBS + kk;
            d[0] = v.x; d[1] = v.y; d[2] = v.z; d[3] = v.w;
        }
        __syncthreads();

#pragma unroll
        for (int kp = 0; kp < BK / 2; ++kp) {
            unsigned long long a2[8], b2[4];
#pragma unroll
            for (int i = 0; i < 8; ++i)
                a2[i] = *(const unsigned long long*)(sA + (ty * 8 + i) * SAS + 2 * kp);
#pragma unroll
            for (int j = 0; j < 4; ++j)
                b2[j] = *(const unsigned long long*)(sB + (tx * 4 + j) * SBS + 2 * kp);
#pragma unroll
            for (int i = 0; i < 8; ++i)
#pragma unroll
                for (int j = 0; j < 4; ++j)
                    ffma2(acc2[i][j], a2[i], b2[j]);
        }
        __syncthreads();
    }

    const int col = c0 + tx * 4;
    float4 bi = *(const float4*)(bih + col);
    float4 bh = *(const float4*)(bhh + col);
    float4 bias;
    bias.x = bi.x + bh.x; bias.y = bi.y + bh.y;
    bias.z = bi.z + bh.z; bias.w = bi.w + bh.w;

#pragma unroll
    for (int i = 0; i < 8; ++i) {
        const int n = n0 + ty * 8 + i;
        const int b = n >> 10;
        const int t = n & 1023;
        float4 o;
        o.x = acc_sum(acc2[i][0]) + bias.x;
        o.y = acc_sum(acc2[i][1]) + bias.y;
        o.z = acc_sum(acc2[i][2]) + bias.z;
        o.w = acc_sum(acc2[i][3]) + bias.w;
        *(float4*)&g_Xg[((size_t)(t * BATCH + b)) * G4 + col] = o;
    }
}

// ======================= Kernel 2: persistent recurrence ===================
// 128 blocks x 128 threads (4 warps). Block owns 8 hidden units = 32 gate rows
// (lr = g*8+u). sWT in SMEM transposed: [kp][lr] float2 (k-even, k-odd).
// Warp w: rows 8w..8w+7. Thread: rg=lane>>4 -> rows rbase=8w+4rg..+3;
// bp=lane&15 -> batches 2bp,2bp+1. 8 f32x2 accumulators (4 rows x 2 batches).
// NOTE: biases are already folded into g_Xg by xg_gemm — do NOT add here.
__global__ __launch_bounds__(NTH, 1) void lstm_rec(const float* __restrict__ Whh,
                                                   float* __restrict__ out) {
    extern __shared__ float smem[];
    float* sWT = smem;                         // KP*64 floats = 128KB: [kp*64 + lr*2 + par]
    float* sH  = smem + KP * 64;               // 2 x KPCH*64 floats = 64KB
    __shared__ float sG[32 * 32];

    const int tid  = threadIdx.x;
    const int blk  = blockIdx.x;
    const int w    = tid >> 5;
    const int lane = tid & 31;
    const int rg   = lane >> 4;
    const int bp   = lane & 15;
    const int rbase = w * 8 + rg * 4;

    // epilogue mapping: bb = tid>>2, uu0 = 2*(tid&3)*... = (2*tid)&7 (even)
    const int bb  = tid >> 2;
    const int uu0 = (2 * tid) & 7;
    const int gu0 = blk * 8 + uu0;

    // ---- init: W transpose into SMEM, zero h[0] ----
    for (int i = tid; i < 32 * (HDIM / 4); i += NTH) {
        const int lr = i >> 8;                  // 256 float4 per row
        const int q  = i & 255;                 // k = 4q..4q+3 -> kp 2q, 2q+1
        const int g = lr >> 3, u = lr & 7;
        const int grow = g * HDIM + blk * 8 + u;
        float4 v = *(const float4*)(Whh + (size_t)grow * HDIM + 4 * q);
        sWT[(2 * q) * 64 + lr * 2]     = v.x;
        sWT[(2 * q) * 64 + lr * 2 + 1] = v.y;
        sWT[(2 * q + 1) * 64 + lr * 2]     = v.z;
        sWT[(2 * q + 1) * 64 + lr * 2 + 1] = v.w;
    }
    // zero own h slice (units uu0, uu0+1 for batch bb)
    *(float2*)&g_h[0][(gu0 >> 1) * 64 + bb * 2] = make_float2(0.f, 0.f);
    float c0s = 0.f, c1s = 0.f;
    __threadfence();
    __syncthreads();

    const unsigned int sHaddr = (unsigned int)__cvta_generic_to_shared(sH);

    for (int t = 0; t < TLEN; ++t) {
        // ---- prefetch Xg for this thread's two cell updates (pre-barrier OK) ----
        const size_t xb = ((size_t)(t * BATCH + bb)) * G4 + blk * 8 + uu0;
        float2 x_i = *(const float2*)(g_Xg + xb);
        float2 x_f = *(const float2*)(g_Xg + xb + HDIM);
        float2 x_g = *(const float2*)(g_Xg + xb + 2 * HDIM);
        float2 x_o = *(const float2*)(g_Xg + xb + 3 * HDIM);

        // ---- grid barrier ----
        __syncthreads();
        if (tid == 0) {
            __threadfence();
            atomicAdd((unsigned*)&g_bar, 1u);
            const unsigned target = (unsigned)(t + 1) * GRID;
            while (g_bar < target) { }
            __threadfence();
        }
        __syncthreads();

        const float* hsrc = g_h[t & 1];
        // issue chunks 0 and 1 (contiguous 32KB copies, 16 x 16B per thread)
#pragma unroll
        for (int j = 0; j < 16; ++j)
            cp16(sHaddr + (unsigned)(tid + j * NTH) * 16u, hsrc + (tid + j * NTH) * 4);
        CP_COMMIT();
#pragma unroll
        for (int j = 0; j < 16; ++j)
            cp16(sHaddr + (unsigned)(KPCH * 64 * 4) + (unsigned)(tid + j * NTH) * 16u,
                 hsrc + KPCH * 64 + (tid + j * NTH) * 4);
        CP_COMMIT();

        unsigned long long A00 = 0, A01 = 0, A10 = 0, A11 = 0,
                           A20 = 0, A21 = 0, A30 = 0, A31 = 0;

#pragma unroll
        for (int c = 0; c < NCH; ++c) {
            if (c < NCH - 1) CP_WAIT(1); else CP_WAIT(0);
            __syncthreads();

            const float* buf = sH + (c & 1) * (KPCH * 64);
            const float* wb  = sWT + (size_t)(c * KPCH) * 64;
#pragma unroll 8
            for (int kpl = 0; kpl < KPCH; ++kpl) {
                ulonglong2 hv  = *(const ulonglong2*)(buf + kpl * 64 + bp * 4);
                ulonglong2 w01 = *(const ulonglong2*)(wb + kpl * 64 + rbase * 2);
                ulonglong2 w23 = *(const ulonglong2*)(wb + kpl * 64 + rbase * 2 + 4);
                ffma2(A00, w01.x, hv.x); ffma2(A01, w01.x, hv.y);
                ffma2(A10, w01.y, hv.x); ffma2(A11, w01.y, hv.y);
                ffma2(A20, w23.x, hv.x); ffma2(A21, w23.x, hv.y);
                ffma2(A30, w23.y, hv.x); ffma2(A31, w23.y, hv.y);
            }
            __syncthreads();
            if (c + 2 < NCH) {
                const float* src = hsrc + (c + 2) * (KPCH * 64);
                const unsigned int dst = sHaddr + (unsigned)((c & 1) * (KPCH * 64 * 4));
#pragma unroll
                for (int j = 0; j < 16; ++j)
                    cp16(dst + (unsigned)(tid + j * NTH) * 16u, src + (tid + j * NTH) * 4);
                CP_COMMIT();
            }
        }

        // ---- publish gate pre-activations [lr][b] ----
        const int b0 = 2 * bp, b1 = 2 * bp + 1;
        sG[(rbase + 0) * 32 + b0] = acc_sum(A00); sG[(rbase + 0) * 32 + b1] = acc_sum(A01);
        sG[(rbase + 1) * 32 + b0] = acc_sum(A10); sG[(rbase + 1) * 32 + b1] = acc_sum(A11);
        sG[(rbase + 2) * 32 + b0] = acc_sum(A20); sG[(rbase + 2) * 32 + b1] = acc_sum(A21);
        sG[(rbase + 3) * 32 + b0] = acc_sum(A30); sG[(rbase + 3) * 32 + b1] = acc_sum(A31);
        __syncthreads();

        // ---- cell updates for (uu0, bb) and (uu0+1, bb); bias is in x_* ----
        const float pi0 = sG[(0 * 8 + uu0) * 32 + bb] + x_i.x;
        const float pf0 = sG[(1 * 8 + uu0) * 32 + bb] + x_f.x;
        const float pg0 = sG[(2 * 8 + uu0) * 32 + bb] + x_g.x;
        const float po0 = sG[(3 * 8 + uu0) * 32 + bb] + x_o.x;
        const float pi1 = sG[(0 * 8 + uu0 + 1) * 32 + bb] + x_i.y;
        const float pf1 = sG[(1 * 8 + uu0 + 1) * 32 + bb] + x_f.y;
        const float pg1 = sG[(2 * 8 + uu0 + 1) * 32 + bb] + x_g.y;
        const float po1 = sG[(3 * 8 + uu0 + 1) * 32 + bb] + x_o.y;

        const float cn0 = fmaf(sigm(pf0), c0s, sigm(pi0) * tanh_f(pg0));
        const float cn1 = fmaf(sigm(pf1), c1s, sigm(pi1) * tanh_f(pg1));
        c0s = cn0; c1s = cn1;
        const float h0 = sigm(po0) * tanh_f(cn0);
        const float h1 = sigm(po1) * tanh_f(cn1);

        *(float2*)&g_h[(t + 1) & 1][(gu0 >> 1) * 64 + bb * 2] = make_float2(h0, h1);
        *(float2*)&out[(size_t)bb * TLEN * HDIM + (size_t)t * HDIM + gu0] = make_float2(h0, h1);
        if (t == TLEN - 1) {
            const size_t OFF = (size_t)BATCH * TLEN * HDIM;
            *(float2*)&out[OFF + (size_t)bb * HDIM + gu0] = make_float2(h0, h1);
            *(float2*)&out[OFF + BATCH * HDIM + (size_t)bb * HDIM + gu0] = make_float2(cn0, cn1);
        }
        __threadfence();
    }

    // ---- reset barrier state for graph replays ----
    __syncthreads();
    if (tid == 0) {
        const unsigned d = atomicAdd(&g_done, 1u);
        if (d == GRID - 1) {
            g_bar = 0;
            g_done = 0;
            __threadfence();
        }
    }
}

// =========================== launch ========================================
extern "C" void kernel_launch(void* const* d_in, const int* in_sizes, int n_in,
                              void* d_out, int out_size) {
    const float* X   = (const float*)d_in[0];
    const float* Wih = (const float*)d_in[1];
    const float* Whh = (const float*)d_in[2];
    const float* bih = (const float*)d_in[3];
    const float* bhh = (const float*)d_in[4];
    float* out = (float*)d_out;

    const int dyn_smem = (KP * 64 + 2 * KPCH * 64) * (int)sizeof(float); // 196608 B
    cudaFuncSetAttribute(lstm_rec, cudaFuncAttributeMaxDynamicSharedMemorySize, dyn_smem);

    xg_gemm<<<dim3(G4 / BN, (BATCH * TLEN) / BM), 256>>>(X, Wih, bih, bhh);
    lstm_rec<<<GRID, NTH, dyn_smem>>>(Whh, out);
}

// round 9
// speedup vs baseline: 1.4933x; 1.0165x over previous
#include <cuda_runtime.h>
#include <cstdint>
#include <math.h>

#define BATCH 32
#define TLEN  1024
#define IDIM  512
#define HDIM  1024
#define G4    4096
#define KP    512          // k-pairs in recurrence (HDIM/2)
#define KPCH  128          // k-pairs per staged chunk
#define NCH   4
#define GRID  128
#define NTH   256

// ---------------- static device scratch (allocation-free) ------------------
__device__ float g_Xg[(size_t)BATCH * TLEN * G4];   // [t*32+b][4096], includes biases
__device__ float g_h[2][HDIM * BATCH];              // [kp][b] float2: idx kp*64 + b*2 + par
__device__ volatile unsigned g_bar;
__device__ unsigned g_done;

// ---------------- helpers ---------------------------------------------------
__device__ __forceinline__ void ffma2(unsigned long long& d,
                                      unsigned long long a,
                                      unsigned long long b) {
    asm("fma.rn.f32x2 %0, %1, %2, %0;" : "+l"(d) : "l"(a), "l"(b));
}
__device__ __forceinline__ float acc_sum(unsigned long long v) {
    return __uint_as_float((unsigned)v) + __uint_as_float((unsigned)(v >> 32));
}
__device__ __forceinline__ float sigm(float x) { return 1.f / (1.f + __expf(-x)); }
__device__ __forceinline__ float tanh_f(float x) { return 1.f - 2.f / (__expf(2.f * x) + 1.f); }

__device__ __forceinline__ void cp16(unsigned int saddr, const void* g) {
    asm volatile("cp.async.cg.shared.global [%0], [%1], 16;" :: "r"(saddr), "l"(g));
}
#define CP_COMMIT() asm volatile("cp.async.commit_group;" ::: "memory")
#define CP_WAIT(n)  asm volatile("cp.async.wait_group %0;" :: "n"(n) : "memory")

// ======================= Kernel 1: Xg = X @ W_ih^T + (b_ih + b_hh) =========
#define BM 128
#define BN 64
#define BK 16
#define SAS 18
#define SBS 18

__global__ __launch_bounds__(256) void xg_gemm(const float* __restrict__ X,
                                               const float* __restrict__ Wih,
                                               const float* __restrict__ bih,
                                               const float* __restrict__ bhh) {
    __shared__ float sA[BM * SAS];
    __shared__ float sB[BN * SBS];

    const int tid = threadIdx.x;
    const int tx = tid & 15;
    const int ty = tid >> 4;
    const int n0 = blockIdx.y * BM;
    const int c0 = blockIdx.x * BN;

    unsigned long long acc2[8][4];
#pragma unroll
    for (int i = 0; i < 8; ++i)
#pragma unroll
        for (int j = 0; j < 4; ++j) acc2[i][j] = 0ull;

    for (int k0 = 0; k0 < IDIM; k0 += BK) {
        {   // A tile: 128x16, 8 floats/thread
            const int m = tid >> 1;
            const int kk = (tid & 1) * 8;
            const float* src = X + (size_t)(n0 + m) * IDIM + k0 + kk;
            float4 v0 = *(const float4*)(src);
            float4 v1 = *(const float4*)(src + 4);
            float* d = sA + m * SAS + kk;
            d[0] = v0.x; d[1] = v0.y; d[2] = v0.z; d[3] = v0.w;
            d[4] = v1.x; d[5] = v1.y; d[6] = v1.z; d[7] = v1.w;
        }
        {   // B tile: 64x16, 4 floats/thread
            const int m = tid >> 2;
            const int kk = (tid & 3) * 4;
            float4 v = *(const float4*)(Wih + (size_t)(c0 + m) * IDIM + k0 + kk);
            float* d = sB + m * SBS + kk;
            d[0] = v.x; d[1] = v.y; d[2] = v.z; d[3] = v.w;
        }
        __syncthreads();

#pragma unroll
        for (int kp = 0; kp < BK / 2; ++kp) {
            unsigned long long a2[8], b2[4];
#pragma unroll
            for (int i = 0; i < 8; ++i)
                a2[i] = *(const unsigned long long*)(sA + (ty * 8 + i) * SAS + 2 * kp);
#pragma unroll
            for (int j = 0; j < 4; ++j)
                b2[j] = *(const unsigned long long*)(sB + (tx * 4 + j) * SBS + 2 * kp);
#pragma unroll
            for (int i = 0; i < 8; ++i)
#pragma unroll
                for (int j = 0; j < 4; ++j)
                    ffma2(acc2[i][j], a2[i], b2[j]);
        }
        __syncthreads();
    }

    const int col = c0 + tx * 4;
    float4 bi = *(const float4*)(bih + col);
    float4 bh = *(const float4*)(bhh + col);
    float4 bias;
    bias.x = bi.x + bh.x; bias.y = bi.y + bh.y;
    bias.z = bi.z + bh.z; bias.w = bi.w + bh.w;

#pragma unroll
    for (int i = 0; i < 8; ++i) {
        const int n = n0 + ty * 8 + i;
        const int b = n >> 10;
        const int t = n & 1023;
        float4 o;
        o.x = acc_sum(acc2[i][0]) + bias.x;
        o.y = acc_sum(acc2[i][1]) + bias.y;
        o.z = acc_sum(acc2[i][2]) + bias.z;
        o.w = acc_sum(acc2[i][3]) + bias.w;
        *(float4*)&g_Xg[((size_t)(t * BATCH + b)) * G4 + col] = o;
    }
}

// ======================= Kernel 2: persistent recurrence ===================
// 128 blocks x 256 threads (8 warps, 2/SMSP). Block owns 8 hidden units = 32
// gate rows. sWT transposed in SMEM: [kp][lr] float2 (k-even, k-odd).
// Warp w: half=w>>2 (K-interleave: kpl = 2*kk+half), wq=w&3 -> rows
// rbase = wq*8 + rg*4 (rg=lane>>4); bp=lane&15 -> batches 2bp,2bp+1.
// Partial sums in sGpart[half], reduced in epilogue. Biases are in g_Xg.
__global__ __launch_bounds__(NTH, 1) void lstm_rec(const float* __restrict__ Whh,
                                                   float* __restrict__ out) {
    extern __shared__ float smem[];
    float* sWT = smem;                         // KP*64 floats = 128KB
    float* sH  = smem + KP * 64;               // 2 x KPCH*64 floats = 64KB
    __shared__ float sGpart[2][32 * 32];

    const int tid  = threadIdx.x;
    const int blk  = blockIdx.x;
    const int w    = tid >> 5;
    const int lane = tid & 31;
    const int half = w >> 2;
    const int wq   = w & 3;
    const int rg   = lane >> 4;
    const int bp   = lane & 15;
    const int rbase = wq * 8 + rg * 4;

    // epilogue mapping: one cell per thread
    const int uu = tid & 7;
    const int bb = tid >> 3;
    const int gu = blk * 8 + uu;

    // ---- init: W transpose into SMEM, zero h[0] ----
    for (int i = tid; i < 32 * (HDIM / 4); i += NTH) {
        const int lr = i >> 8;                  // 256 float4 per row
        const int q  = i & 255;                 // k = 4q..4q+3 -> kp 2q, 2q+1
        const int g = lr >> 3, u = lr & 7;
        const int grow = g * HDIM + blk * 8 + u;
        float4 v = *(const float4*)(Whh + (size_t)grow * HDIM + 4 * q);
        sWT[(2 * q) * 64 + lr * 2]     = v.x;
        sWT[(2 * q) * 64 + lr * 2 + 1] = v.y;
        sWT[(2 * q + 1) * 64 + lr * 2]     = v.z;
        sWT[(2 * q + 1) * 64 + lr * 2 + 1] = v.w;
    }
    g_h[0][(gu >> 1) * 64 + bb * 2 + (gu & 1)] = 0.f;
    float cs = 0.f;
    __threadfence();
    __syncthreads();

    const unsigned int sHaddr = (unsigned int)__cvta_generic_to_shared(sH);

    for (int t = 0; t < TLEN; ++t) {
        // ---- prefetch Xg for this thread's cell (pre-barrier OK) ----
        const size_t xb = ((size_t)(t * BATCH + bb)) * G4 + blk * 8 + uu;
        const float x_i = g_Xg[xb];
        const float x_f = g_Xg[xb + HDIM];
        const float x_g = g_Xg[xb + 2 * HDIM];
        const float x_o = g_Xg[xb + 3 * HDIM];

        // ---- grid barrier ----
        __syncthreads();
        if (tid == 0) {
            __threadfence();
            atomicAdd((unsigned*)&g_bar, 1u);
            const unsigned target = (unsigned)(t + 1) * GRID;
            while (g_bar < target) { }
            __threadfence();
        }
        __syncthreads();

        const float* hsrc = g_h[t & 1];
        // issue chunks 0 and 1 (32KB each = 2048 float4; 8 per thread)
#pragma unroll
        for (int j = 0; j < 8; ++j)
            cp16(sHaddr + (unsigned)(tid + j * NTH) * 16u, hsrc + (tid + j * NTH) * 4);
        CP_COMMIT();
#pragma unroll
        for (int j = 0; j < 8; ++j)
            cp16(sHaddr + (unsigned)(KPCH * 64 * 4) + (unsigned)(tid + j * NTH) * 16u,
                 hsrc + KPCH * 64 + (tid + j * NTH) * 4);
        CP_COMMIT();

        unsigned long long A00 = 0, A01 = 0, A10 = 0, A11 = 0,
                           A20 = 0, A21 = 0, A30 = 0, A31 = 0;

#pragma unroll
        for (int c = 0; c < NCH; ++c) {
            if (c < NCH - 1) CP_WAIT(1); else CP_WAIT(0);
            __syncthreads();

            const float* buf = sH + (c & 1) * (KPCH * 64);
            const float* wb  = sWT + (size_t)(c * KPCH) * 64;
#pragma unroll 8
            for (int kk = 0; kk < KPCH / 2; ++kk) {
                const int kpl = 2 * kk + half;
                ulonglong2 hv  = *(const ulonglong2*)(buf + kpl * 64 + bp * 4);
                ulonglong2 w01 = *(const ulonglong2*)(wb + kpl * 64 + rbase * 2);
                ulonglong2 w23 = *(const ulonglong2*)(wb + kpl * 64 + rbase * 2 + 4);
                ffma2(A00, w01.x, hv.x); ffma2(A01, w01.x, hv.y);
                ffma2(A10, w01.y, hv.x); ffma2(A11, w01.y, hv.y);
                ffma2(A20, w23.x, hv.x); ffma2(A21, w23.x, hv.y);
                ffma2(A30, w23.y, hv.x); ffma2(A31, w23.y, hv.y);
            }
            __syncthreads();
            if (c + 2 < NCH) {
                const float* src = hsrc + (c + 2) * (KPCH * 64);
                const unsigned int dst = sHaddr + (unsigned)((c & 1) * (KPCH * 64 * 4));
#pragma unroll
                for (int j = 0; j < 8; ++j)
                    cp16(dst + (unsigned)(tid + j * NTH) * 16u, src + (tid + j * NTH) * 4);
                CP_COMMIT();
            }
        }

        // ---- publish partial gate pre-activations [half][lr][b] ----
        {
            float* gp = sGpart[half];
            const int b0 = 2 * bp, b1 = 2 * bp + 1;
            gp[(rbase + 0) * 32 + b0] = acc_sum(A00); gp[(rbase + 0) * 32 + b1] = acc_sum(A01);
            gp[(rbase + 1) * 32 + b0] = acc_sum(A10); gp[(rbase + 1) * 32 + b1] = acc_sum(A11);
            gp[(rbase + 2) * 32 + b0] = acc_sum(A20); gp[(rbase + 2) * 32 + b1] = acc_sum(A21);
            gp[(rbase + 3) * 32 + b0] = acc_sum(A30); gp[(rbase + 3) * 32 + b1] = acc_sum(A31);
        }
        __syncthreads();

        // ---- cell update: thread (uu, bb); bias already in x_* ----
        const float pi = sGpart[0][(0 * 8 + uu) * 32 + bb] + sGpart[1][(0 * 8 + uu) * 32 + bb] + x_i;
        const float pf = sGpart[0][(1 * 8 + uu) * 32 + bb] + sGpart[1][(1 * 8 + uu) * 32 + bb] + x_f;
        const float pg = sGpart[0][(2 * 8 + uu) * 32 + bb] + sGpart[1][(2 * 8 + uu) * 32 + bb] + x_g;
        const float po = sGpart[0][(3 * 8 + uu) * 32 + bb] + sGpart[1][(3 * 8 + uu) * 32 + bb] + x_o;

        const float cn = fmaf(sigm(pf), cs, sigm(pi) * tanh_f(pg));
        cs = cn;
        const float hn = sigm(po) * tanh_f(cn);

        g_h[(t + 1) & 1][(gu >> 1) * 64 + bb * 2 + (gu & 1)] = hn;
        out[(size_t)bb * TLEN * HDIM + (size_t)t * HDIM + gu] = hn;
        if (t == TLEN - 1) {
            const size_t OFF = (size_t)BATCH * TLEN * HDIM;
            out[OFF + (size_t)bb * HDIM + gu] = hn;                  // h_T
            out[OFF + BATCH * HDIM + (size_t)bb * HDIM + gu] = cn;   // c_T
        }
        __threadfence();
    }

    // ---- reset barrier state for graph replays ----
    __syncthreads();
    if (tid == 0) {
        const unsigned d = atomicAdd(&g_done, 1u);
        if (d == GRID - 1) {
            g_bar = 0;
            g_done = 0;
            __threadfence();
        }
    }
}

// =========================== launch ========================================
extern "C" void kernel_launch(void* const* d_in, const int* in_sizes, int n_in,
                              void* d_out, int out_size) {
    const float* X   = (const float*)d_in[0];
    const float* Wih = (const float*)d_in[1];
    const float* Whh = (const float*)d_in[2];
    const float* bih = (const float*)d_in[3];
    const float* bhh = (const float*)d_in[4];
    float* out = (float*)d_out;

    const int dyn_smem = (KP * 64 + 2 * KPCH * 64) * (int)sizeof(float); // 196608 B
    cudaFuncSetAttribute(lstm_rec, cudaFuncAttributeMaxDynamicSharedMemorySize, dyn_smem);

    xg_gemm<<<dim3(G4 / BN, (BATCH * TLEN) / BM), 256>>>(X, Wih, bih, bhh);
    lstm_rec<<<GRID, NTH, dyn_smem>>>(Whh, out);
}

// round 11
// speedup vs baseline: 1.5354x; 1.0282x over previous
#include <cuda_runtime.h>
#include <cstdint>
#include <math.h>

#define BATCH 32
#define TLEN  1024
#define IDIM  512
#define HDIM  1024
#define G4    4096
#define KP    512          // k-pairs in recurrence (HDIM/2)
#define KPCH  128          // k-pairs per staged chunk
#define NCH   4
#define GRID  128
#define NTH   512

// ---------------- static device scratch (allocation-free) ------------------
__device__ float g_Xg[(size_t)BATCH * TLEN * G4];   // [t*32+b][4096], includes biases
__device__ float g_h[2][HDIM * BATCH];              // [kp][b] float2: idx kp*64 + b*2 + par
__device__ volatile unsigned g_bar;
__device__ unsigned g_done;

// ---------------- helpers ---------------------------------------------------
__device__ __forceinline__ void ffma2(unsigned long long& d,
                                      unsigned long long a,
                                      unsigned long long b) {
    asm("fma.rn.f32x2 %0, %1, %2, %0;" : "+l"(d) : "l"(a), "l"(b));
}
__device__ __forceinline__ float acc_sum(unsigned long long v) {
    return __uint_as_float((unsigned)v) + __uint_as_float((unsigned)(v >> 32));
}
__device__ __forceinline__ float sigm(float x) { return 1.f / (1.f + __expf(-x)); }
__device__ __forceinline__ float tanh_f(float x) { return 1.f - 2.f / (__expf(2.f * x) + 1.f); }

__device__ __forceinline__ void cp16(unsigned int saddr, const void* g) {
    asm volatile("cp.async.cg.shared.global [%0], [%1], 16;" :: "r"(saddr), "l"(g));
}
#define CP_COMMIT() asm volatile("cp.async.commit_group;" ::: "memory")
#define CP_WAIT(n)  asm volatile("cp.async.wait_group %0;" :: "n"(n) : "memory")

// ======================= Kernel 1: Xg = X @ W_ih^T + (b_ih + b_hh) =========
#define BM 128
#define BN 64
#define BK 16
#define SAS 18
#define SBS 18

__global__ __launch_bounds__(256) void xg_gemm(const float* __restrict__ X,
                                               const float* __restrict__ Wih,
                                               const float* __restrict__ bih,
                                               const float* __restrict__ bhh) {
    __shared__ float sA[BM * SAS];
    __shared__ float sB[BN * SBS];

    const int tid = threadIdx.x;
    const int tx = tid & 15;
    const int ty = tid >> 4;
    const int n0 = blockIdx.y * BM;
    const int c0 = blockIdx.x * BN;

    unsigned long long acc2[8][4];
#pragma unroll
    for (int i = 0; i < 8; ++i)
#pragma unroll
        for (int j = 0; j < 4; ++j) acc2[i][j] = 0ull;

    for (int k0 = 0; k0 < IDIM; k0 += BK) {
        {   // A tile: 128x16, 8 floats/thread
            const int m = tid >> 1;
            const int kk = (tid & 1) * 8;
            const float* src = X + (size_t)(n0 + m) * IDIM + k0 + kk;
            float4 v0 = *(const float4*)(src);
            float4 v1 = *(const float4*)(src + 4);
            float* d = sA + m * SAS + kk;
            d[0] = v0.x; d[1] = v0.y; d[2] = v0.z; d[3] = v0.w;
            d[4] = v1.x; d[5] = v1.y; d[6] = v1.z; d[7] = v1.w;
        }
        {   // B tile: 64x16, 4 floats/thread
            const int m = tid >> 2;
            const int kk = (tid & 3) * 4;
            float4 v = *(const float4*)(Wih + (size_t)(c0 + m) * IDIM + k0 + kk);
            float* d = sB + m * SBS + kk;
            d[0] = v.x; d[1] = v.y; d[2] = v.z; d[3] = v.w;
        }
        __syncthreads();

#pragma unroll
        for (int kp = 0; kp < BK / 2; ++kp) {
            unsigned long long a2[8], b2[4];
#pragma unroll
            for (int i = 0; i < 8; ++i)
                a2[i] = *(const unsigned long long*)(sA + (ty * 8 + i) * SAS + 2 * kp);
#pragma unroll
            for (int j = 0; j < 4; ++j)
                b2[j] = *(const unsigned long long*)(sB + (tx * 4 + j) * SBS + 2 * kp);
#pragma unroll
            for (int i = 0; i < 8; ++i)
#pragma unroll
                for (int j = 0; j < 4; ++j)
                    ffma2(acc2[i][j], a2[i], b2[j]);
        }
        __syncthreads();
    }

    const int col = c0 + tx * 4;
    float4 bi = *(const float4*)(bih + col);
    float4 bh = *(const float4*)(bhh + col);
    float4 bias;
    bias.x = bi.x + bh.x; bias.y = bi.y + bh.y;
    bias.z = bi.z + bh.z; bias.w = bi.w + bh.w;

#pragma unroll
    for (int i = 0; i < 8; ++i) {
        const int n = n0 + ty * 8 + i;
        const int b = n >> 10;
        const int t = n & 1023;
        float4 o;
        o.x = acc_sum(acc2[i][0]) + bias.x;
        o.y = acc_sum(acc2[i][1]) + bias.y;
        o.z = acc_sum(acc2[i][2]) + bias.z;
        o.w = acc_sum(acc2[i][3]) + bias.w;
        *(float4*)&g_Xg[((size_t)(t * BATCH + b)) * G4 + col] = o;
    }
}

// ======================= Kernel 2: persistent recurrence ===================
// 128 blocks x 512 threads (16 warps, 4/SMSP). Block owns 8 hidden units = 32
// gate rows. sWT transposed in SMEM: [kp][lr] float2 (k-even, k-odd).
// Warp w: quarter=w>>2 (K-interleave: kpl = 4*kk+quarter), wq=w&3 -> rows
// rbase = wq*8 + rg*4 (rg=lane>>4); bp=lane&15 -> batches 2bp,2bp+1.
// Partial sums in sGpart[quarter] (stride-33 rows), reduced by tid<256.
// Biases are folded into g_Xg. No per-thread fences: loop-top __syncthreads +
// tid0 fence-before-arrive forms the release chain for h stores.
#define GSTR 33
__global__ __launch_bounds__(NTH, 1) void lstm_rec(const float* __restrict__ Whh,
                                                   float* __restrict__ out) {
    extern __shared__ float smem[];
    float* sWT = smem;                         // KP*64 floats = 128KB
    float* sH  = smem + KP * 64;               // 2 x KPCH*64 floats = 64KB
    __shared__ float sGpart[4][32 * GSTR];

    const int tid  = threadIdx.x;
    const int blk  = blockIdx.x;
    const int w    = tid >> 5;
    const int lane = tid & 31;
    const int quarter = w >> 2;
    const int wq   = w & 3;
    const int rg   = lane >> 4;
    const int bp   = lane & 15;
    const int rbase = wq * 8 + rg * 4;

    // epilogue mapping (tid < 256): one cell per thread
    const int uu = tid & 7;
    const int bb = (tid >> 3) & 31;
    const int gu = blk * 8 + uu;

    // ---- init: W transpose into SMEM, zero h[0] ----
    for (int i = tid; i < 32 * (HDIM / 4); i += NTH) {
        const int lr = i >> 8;                  // 256 float4 per row
        const int q  = i & 255;                 // k = 4q..4q+3 -> kp 2q, 2q+1
        const int g = lr >> 3, u = lr & 7;
        const int grow = g * HDIM + blk * 8 + u;
        float4 v = *(const float4*)(Whh + (size_t)grow * HDIM + 4 * q);
        sWT[(2 * q) * 64 + lr * 2]     = v.x;
        sWT[(2 * q) * 64 + lr * 2 + 1] = v.y;
        sWT[(2 * q + 1) * 64 + lr * 2]     = v.z;
        sWT[(2 * q + 1) * 64 + lr * 2 + 1] = v.w;
    }
    if (tid < 256) g_h[0][(gu >> 1) * 64 + bb * 2 + (gu & 1)] = 0.f;
    float cs = 0.f;
    __threadfence();
    __syncthreads();

    const unsigned int sHaddr = (unsigned int)__cvta_generic_to_shared(sH);

    for (int t = 0; t < TLEN; ++t) {
        // ---- prefetch Xg for this thread's cell (pre-barrier OK) ----
        float x_i = 0.f, x_f = 0.f, x_g = 0.f, x_o = 0.f;
        if (tid < 256) {
            const size_t xb = ((size_t)(t * BATCH + bb)) * G4 + blk * 8 + uu;
            x_i = g_Xg[xb];
            x_f = g_Xg[xb + HDIM];
            x_g = g_Xg[xb + 2 * HDIM];
            x_o = g_Xg[xb + 3 * HDIM];
        }

        // ---- grid barrier (release: h stores ordered by this sync+fence) ----
        __syncthreads();
        if (tid == 0) {
            __threadfence();
            atomicAdd((unsigned*)&g_bar, 1u);
            const unsigned target = (unsigned)(t + 1) * GRID;
            while (g_bar < target) { }
            __threadfence();
        }
        __syncthreads();

        const float* hsrc = g_h[t & 1];
        // issue chunks 0 and 1 (32KB each = 2048 float4; 4 per thread)
#pragma unroll
        for (int j = 0; j < 4; ++j)
            cp16(sHaddr + (unsigned)(tid + j * NTH) * 16u, hsrc + (tid + j * NTH) * 4);
        CP_COMMIT();
#pragma unroll
        for (int j = 0; j < 4; ++j)
            cp16(sHaddr + (unsigned)(KPCH * 64 * 4) + (unsigned)(tid + j * NTH) * 16u,
                 hsrc + KPCH * 64 + (tid + j * NTH) * 4);
        CP_COMMIT();

        unsigned long long A00 = 0, A01 = 0, A10 = 0, A11 = 0,
                           A20 = 0, A21 = 0, A30 = 0, A31 = 0;

#pragma unroll
        for (int c = 0; c < NCH; ++c) {
            if (c < NCH - 1) CP_WAIT(1); else CP_WAIT(0);
            __syncthreads();

            const float* buf = sH + (c & 1) * (KPCH * 64);
            const float* wb  = sWT + (size_t)(c * KPCH) * 64;
#pragma unroll 8
            for (int kk = 0; kk < KPCH / 4; ++kk) {
                const int kpl = 4 * kk + quarter;
                ulonglong2 hv  = *(const ulonglong2*)(buf + kpl * 64 + bp * 4);
                ulonglong2 w01 = *(const ulonglong2*)(wb + kpl * 64 + rbase * 2);
                ulonglong2 w23 = *(const ulonglong2*)(wb + kpl * 64 + rbase * 2 + 4);
                ffma2(A00, w01.x, hv.x); ffma2(A01, w01.x, hv.y);
                ffma2(A10, w01.y, hv.x); ffma2(A11, w01.y, hv.y);
                ffma2(A20, w23.x, hv.x); ffma2(A21, w23.x, hv.y);
                ffma2(A30, w23.y, hv.x); ffma2(A31, w23.y, hv.y);
            }
            __syncthreads();
            if (c + 2 < NCH) {
                const float* src = hsrc + (c + 2) * (KPCH * 64);
                const unsigned int dst = sHaddr + (unsigned)((c & 1) * (KPCH * 64 * 4));
#pragma unroll
                for (int j = 0; j < 4; ++j)
                    cp16(dst + (unsigned)(tid + j * NTH) * 16u, src + (tid + j * NTH) * 4);
                CP_COMMIT();
            }
        }

        // ---- publish partial gate pre-activations [quarter][lr][b] ----
        {
            float* gp = sGpart[quarter];
            const int b0 = 2 * bp, b1 = 2 * bp + 1;
            gp[(rbase + 0) * GSTR + b0] = acc_sum(A00); gp[(rbase + 0) * GSTR + b1] = acc_sum(A01);
            gp[(rbase + 1) * GSTR + b0] = acc_sum(A10); gp[(rbase + 1) * GSTR + b1] = acc_sum(A11);
            gp[(rbase + 2) * GSTR + b0] = acc_sum(A20); gp[(rbase + 2) * GSTR + b1] = acc_sum(A21);
            gp[(rbase + 3) * GSTR + b0] = acc_sum(A30); gp[(rbase + 3) * GSTR + b1] = acc_sum(A31);
        }
        __syncthreads();

        // ---- cell update: threads 0..255, one (uu, bb) each ----
        if (tid < 256) {
            const int ri = (0 * 8 + uu) * GSTR + bb;
            const int rf = (1 * 8 + uu) * GSTR + bb;
            const int rgi = (2 * 8 + uu) * GSTR + bb;
            const int ro = (3 * 8 + uu) * GSTR + bb;
            const float pi = sGpart[0][ri] + sGpart[1][ri] + sGpart[2][ri] + sGpart[3][ri] + x_i;
            const float pf = sGpart[0][rf] + sGpart[1][rf] + sGpart[2][rf] + sGpart[3][rf] + x_f;
            const float pg = sGpart[0][rgi] + sGpart[1][rgi] + sGpart[2][rgi] + sGpart[3][rgi] + x_g;
            const float po = sGpart[0][ro] + sGpart[1][ro] + sGpart[2][ro] + sGpart[3][ro] + x_o;

            const float cn = fmaf(sigm(pf), cs, sigm(pi) * tanh_f(pg));
            cs = cn;
            const float hn = sigm(po) * tanh_f(cn);

            g_h[(t + 1) & 1][(gu >> 1) * 64 + bb * 2 + (gu & 1)] = hn;
            out[(size_t)bb * TLEN * HDIM + (size_t)t * HDIM + gu] = hn;
            if (t == TLEN - 1) {
                const size_t OFF = (size_t)BATCH * TLEN * HDIM;
                out[OFF + (size_t)bb * HDIM + gu] = hn;                  // h_T
                out[OFF + BATCH * HDIM + (size_t)bb * HDIM + gu] = cn;   // c_T
            }
        }
        // no trailing fence: next iteration's __syncthreads + tid0 fence
        // publish the h stores before the barrier arrival.
    }

    // ---- reset barrier state for graph replays ----
    __syncthreads();
    if (tid == 0) {
        const unsigned d = atomicAdd(&g_done, 1u);
        if (d == GRID - 1) {
            g_bar = 0;
            g_done = 0;
            __threadfence();
        }
    }
}

// =========================== launch ========================================
extern "C" void kernel_launch(void* const* d_in, const int* in_sizes, int n_in,
                              void* d_out, int out_size) {
    const float* X   = (const float*)d_in[0];
    const float* Wih = (const float*)d_in[1];
    const float* Whh = (const float*)d_in[2];
    const float* bih = (const float*)d_in[3];
    const float* bhh = (const float*)d_in[4];
    float* out = (float*)d_out;

    const int dyn_smem = (KP * 64 + 2 * KPCH * 64) * (int)sizeof(float); // 196608 B
    cudaFuncSetAttribute(lstm_rec, cudaFuncAttributeMaxDynamicSharedMemorySize, dyn_smem);

    xg_gemm<<<dim3(G4 / BN, (BATCH * TLEN) / BM), 256>>>(X, Wih, bih, bhh);
    lstm_rec<<<GRID, NTH, dyn_smem>>>(Whh, out);
}